// round 13
// baseline (speedup 1.0000x reference)
#include <cuda_runtime.h>
#include <cuda_bf16.h>
#include <cstdint>

typedef unsigned long long u64;

// ---------------- packed fp32 + cluster helpers (sm_103a) ----------------
__device__ __forceinline__ u64 dup2(float x) {
    u64 r; asm("mov.b64 %0, {%1, %1};" : "=l"(r) : "f"(x)); return r;
}
__device__ __forceinline__ u64 fma2(u64 a, u64 b, u64 c) {
    u64 d; asm("fma.rn.f32x2 %0, %1, %2, %3;" : "=l"(d) : "l"(a), "l"(b), "l"(c));
    return d;
}
__device__ __forceinline__ u64 add2(u64 a, u64 b) {
    u64 d; asm("add.rn.f32x2 %0, %1, %2;" : "=l"(d) : "l"(a), "l"(b));
    return d;
}
__device__ __forceinline__ void unpack2(float& lo, float& hi, u64 v) {
    asm("mov.b64 {%0, %1}, %2;" : "=f"(lo), "=f"(hi) : "l"(v));
}
__device__ __forceinline__ u64 shfl_bfly_u64(u64 v, int m) {
    uint32_t lo, hi;
    asm("mov.b64 {%0, %1}, %2;" : "=r"(lo), "=r"(hi) : "l"(v));
    lo = __shfl_xor_sync(0xffffffffu, lo, m);
    hi = __shfl_xor_sync(0xffffffffu, hi, m);
    u64 r; asm("mov.b64 %0, {%1, %2};" : "=l"(r) : "r"(lo), "r"(hi));
    return r;
}
__device__ __forceinline__ uint32_t smem_u32(const void* p) {
    uint32_t a;
    asm("{ .reg .u64 t0; cvta.to.shared.u64 t0, %1; cvt.u32.u64 %0, t0; }"
        : "=r"(a) : "l"(p));
    return a;
}
__device__ __forceinline__ uint32_t mapa32(uint32_t saddr, uint32_t rank) {
    uint32_t r_;
    asm("mapa.shared::cluster.u32 %0, %1, %2;" : "=r"(r_) : "r"(saddr), "r"(rank));
    return r_;
}
__device__ __forceinline__ void st_cluster_v4(uint32_t addr, float4 v) {
    asm volatile("st.shared::cluster.v4.f32 [%0], {%1,%2,%3,%4};"
                 :: "r"(addr), "f"(v.x), "f"(v.y), "f"(v.z), "f"(v.w) : "memory");
}
__device__ __forceinline__ void mbar_init(uint32_t addr, uint32_t count) {
    asm volatile("mbarrier.init.shared.b64 [%0], %1;" :: "r"(addr), "r"(count) : "memory");
}
__device__ __forceinline__ void mbar_arrive_rel(uint32_t raddr) {
    asm volatile("mbarrier.arrive.release.cluster.shared::cluster.b64 _, [%0];"
                 :: "r"(raddr) : "memory");
}
__device__ __forceinline__ void mbar_wait_acq(uint32_t mbar, uint32_t parity) {
    asm volatile(
        "{\n\t"
        ".reg .pred P;\n\t"
        "MW_%=:\n\t"
        "mbarrier.try_wait.parity.acquire.cluster.shared::cta.b64 P, [%0], %1, 0x989680;\n\t"
        "@P bra.uni MD_%=;\n\t"
        "bra.uni MW_%=;\n\t"
        "MD_%=:\n\t"
        "}"
        :: "r"(mbar), "r"(parity) : "memory");
}
__device__ __forceinline__ uint32_t ctarank() {
    uint32_t r; asm("mov.u32 %0, %%cluster_ctarank;" : "=r"(r)); return r;
}
__device__ __forceinline__ void cluster_sync_() {
    asm volatile("barrier.cluster.arrive.aligned;" ::: "memory");
    asm volatile("barrier.cluster.wait.aligned;" ::: "memory");
}
// fast tanh: clamp then (e^2s - 1)/(e^2s + 1)
__device__ __forceinline__ float tanh_fast(float s) {
    float sc = fminf(fmaxf(s, -15.0f), 15.0f);
    float e  = __expf(2.0f * sc);
    return __fdividef(e - 1.0f, e + 1.0f);
}

// =====================================================================
// Kernel 1: out = inputs @ W_xh + b_h   (M=65536, K=256, N=512)
// =====================================================================
__global__ void __launch_bounds__(256)
xw_gemm_kernel(const float* __restrict__ A, const float* __restrict__ B,
               const float* __restrict__ bias, float* __restrict__ C) {
    __shared__ __align__(16) float As[8][128];
    __shared__ __align__(16) float Bs[8][128];
    const int tid = threadIdx.x;
    const int bn  = blockIdx.x;
    const int bm  = blockIdx.y;
    const int tx  = tid & 15;
    const int ty  = tid >> 4;
    const int arow = tid >> 1, acol = (tid & 1) << 2;
    const int brow = tid >> 5, bcol = (tid & 31) << 2;
    const float* Ab = A + (size_t)bm * 128 * 256;
    const float* Bb = B + bn * 128;

    u64 acc2[8][4];
#pragma unroll
    for (int i = 0; i < 8; i++)
#pragma unroll
        for (int j = 0; j < 4; j++) acc2[i][j] = 0ull;

    for (int k0 = 0; k0 < 256; k0 += 8) {
        float4 av = *(const float4*)(Ab + (size_t)arow * 256 + k0 + acol);
        As[acol + 0][arow] = av.x;
        As[acol + 1][arow] = av.y;
        As[acol + 2][arow] = av.z;
        As[acol + 3][arow] = av.w;
        *(float4*)&Bs[brow][bcol] =
            *(const float4*)(Bb + (size_t)(k0 + brow) * 512 + bcol);
        __syncthreads();
#pragma unroll
        for (int k = 0; k < 8; k++) {
            float4 a0 = *(const float4*)&As[k][ty * 8];
            float4 a1 = *(const float4*)&As[k][ty * 8 + 4];
            const u64* bp = (const u64*)&Bs[k][tx * 8];
            u64 b2[4];
#pragma unroll
            for (int j = 0; j < 4; j++) b2[j] = bp[j];
            u64 ad[8];
            ad[0] = dup2(a0.x); ad[1] = dup2(a0.y);
            ad[2] = dup2(a0.z); ad[3] = dup2(a0.w);
            ad[4] = dup2(a1.x); ad[5] = dup2(a1.y);
            ad[6] = dup2(a1.z); ad[7] = dup2(a1.w);
#pragma unroll
            for (int i = 0; i < 8; i++)
#pragma unroll
                for (int j = 0; j < 4; j++)
                    acc2[i][j] = fma2(ad[i], b2[j], acc2[i][j]);
        }
        __syncthreads();
    }

    float bi[8];
#pragma unroll
    for (int j = 0; j < 8; j++) bi[j] = bias[bn * 128 + tx * 8 + j];
#pragma unroll
    for (int i = 0; i < 8; i++) {
        size_t row = (size_t)bm * 128 + ty * 8 + i;
        float* cp = C + row * 512 + bn * 128 + tx * 8;
        float v[8];
#pragma unroll
        for (int j = 0; j < 4; j++) unpack2(v[2 * j], v[2 * j + 1], acc2[i][j]);
#pragma unroll
        for (int j = 0; j < 8; j++) v[j] += bi[j];
        *(float4*)(cp + 0) = make_float4(v[0], v[1], v[2], v[3]);
        *(float4*)(cp + 4) = make_float4(v[4], v[5], v[6], v[7]);
    }
}

// =====================================================================
// Kernel 2: recurrence. 32 clusters x 8 CTAs x 256 threads, 2 CTAs/SM.
// Per-slice mbarrier dataflow; ONE __syncthreads per step.
// GEMV (R11 tiling) + shfl.bfly(16) half-combine -> 8 partials.
// red is DOUBLE-BUFFERED by step parity (fast warps of step t+1 must
// not overwrite partials still being read at step t).
// Reducers (tid<128, rb=tid&1, rc=tid>>1) compute h, STG out, then
// even lanes shfl-pack the dup'd float4 and send it straight to all
// 8 ranks (register->DSMEM, no staging), then release-arrive.
// full[b][src] count = 64 (even reducer lanes of CTA src).
// =====================================================================
// float offsets in dynamic smem
#define WSM_OFF  0            // [8][64][16] u64 = 16384 floats (64 KB)
#define HB_OFF   16384        // [2][512][4] dup'd h = 4096 floats (16 KB)
#define RED_OFF  20480        // [2][16][33] u64 = 2112 floats
#define MB_OFF   (RED_OFF + 2112)          // full[2][8] = 16 mbarriers
#define K2_FLOATS (MB_OFF + 32)
#define K2_SMEM_BYTES (K2_FLOATS * 4)      // 90,496 B

__global__ void __launch_bounds__(256, 2) __cluster_dims__(8, 1, 1)
rnn_rec_kernel(const float* __restrict__ W_hh, float* __restrict__ out) {
    extern __shared__ __align__(16) float smem[];
    u64*   wsm = (u64*)(smem + WSM_OFF);
    float* hb  = smem + HB_OFF;
    float* red = smem + RED_OFF;

    const int tid = threadIdx.x;
    const uint32_t rr = ctarank();
    const int w    = tid >> 5;          // warp 0..7
    const int ln   = tid & 31;
    const int half = ln >> 4;
    const int l15  = ln & 15;
    const int cluster = (int)(blockIdx.x >> 3);

    const int kbase = 64 * w + 32 * half;
    const int c0    = 4 * l15;

    // ---- W: col-pair A in regs; col-pair B in smem ----
    u64 wregA[32];
    {
        const u64* wgA = (const u64*)(W_hh + (size_t)kbase * 512 +
                                      rr * 64 + c0);
#pragma unroll
        for (int kk = 0; kk < 32; kk++) wregA[kk] = wgA[(size_t)kk * 256];
        const u64* wgB = (const u64*)(W_hh + (size_t)kbase * 512 +
                                      rr * 64 + c0 + 2);
        for (int kk = 0; kk < 32; kk++)
            wsm[(size_t)(w * 64 + half * 32 + kk) * 16 + l15] =
                wgB[(size_t)kk * 256];
    }
    for (int i = tid; i < 4096; i += 256) hb[i] = 0.0f;

    // ---- mbarriers: full[2][8], count 64 (even reducer lanes) ----
    const uint32_t mb_s = smem_u32(smem + MB_OFF);
    if (tid == 0) {
#pragma unroll
        for (int b = 0; b < 2; b++)
            for (int s = 0; s < 8; s++)
                mbar_init(mb_s + (b * 8 + s) * 8, 64);
    }
    __syncthreads();
    cluster_sync_();   // peers' inits + hb zeros visible before any remote op

    // reducer/sender mapping (tid < 128): batch rb, col rc
    const int rb = tid & 1;
    const int rc = tid >> 1;

    const uint32_t hb_s = smem_u32(hb);
    const uint32_t fullW0 = mb_s + (0 * 8 + w) * 8;
    const uint32_t fullW1 = mb_s + (1 * 8 + w) * 8;

    u64* redu = (u64*)red;
    const int hslot = w * 2;            // combined: one slot pair per warp
    const int P0 = 2 * l15;
    const size_t obase = ((size_t)(cluster * 2 + rb) * 1024) * 512 +
                         (size_t)rr * 64 + rc;
    const u64* wqB = wsm + (size_t)(w * 64 + half * 32) * 16 + l15;

    float xw_next = (tid < 128) ? out[obase] : 0.0f;

    int phF0 = 0, phF1 = 0;

    for (int t = 0; t < 1024; t++) {
        const int j  = t & 1;
        const int jr = j ^ 1;
        const float xw_v = xw_next;
        const size_t oidx = obase + (size_t)t * 512;

        // ---- wait only MY slice (from rank w) ----
        if (t > 0) {
            if (jr == 0) { mbar_wait_acq(fullW0, phF0); phF0 ^= 1; }
            else         { mbar_wait_acq(fullW1, phF1); phF1 ^= 1; }
        }

        // ---- GEMV: 2 col-pairs x 32 k per lane ----
        u64 aA0 = 0ull, aB0 = 0ull, aA1 = 0ull, aB1 = 0ull;
        const ulonglong2* hp =
            (const ulonglong2*)(hb + (size_t)(jr * 512 + kbase) * 4);
#pragma unroll
        for (int kk = 0; kk < 32; kk++) {
            ulonglong2 hv = hp[kk];          // {dup(h b0), dup(h b1)}
            u64 wA = wregA[kk];
            u64 wB = wqB[(size_t)kk * 16];
            aA0 = fma2(wA, hv.x, aA0);
            aB0 = fma2(wA, hv.y, aB0);
            aA1 = fma2(wB, hv.x, aA1);
            aB1 = fma2(wB, hv.y, aB1);
        }
        // combine the two k-halves (same cols) within the warp
        aA0 = add2(aA0, shfl_bfly_u64(aA0, 16));
        aB0 = add2(aB0, shfl_bfly_u64(aB0, 16));
        aA1 = add2(aA1, shfl_bfly_u64(aA1, 16));
        aB1 = add2(aB1, shfl_bfly_u64(aB1, 16));
        if (half == 0) {
            u64* rj = redu + j * 528;   // double-buffered partials
            rj[(hslot + 0) * 33 + P0]     = aA0;
            rj[(hslot + 1) * 33 + P0]     = aB0;
            rj[(hslot + 0) * 33 + P0 + 1] = aA1;
            rj[(hslot + 1) * 33 + P0 + 1] = aB1;
        }
        __syncthreads();   // the ONLY per-step CTA sync

        // ---- reduce 8 partials + xw, tanh, STG, send from registers ----
        if (tid < 128) {
            const float* rj = red + j * 1056;
            float s = xw_v;
#pragma unroll
            for (int ww = 0; ww < 8; ww++)
                s += rj[(ww * 2 + rb) * 66 + rc];
            float h = tanh_fast(s);
            out[oidx] = h;

            if (t < 1023) {
                u64 myd = dup2(h);
                u64 od  = shfl_bfly_u64(myd, 1);  // partner batch's dup'd h
                if (rb == 0) {
                    float plo, phi; unpack2(plo, phi, od);
                    float4 v = make_float4(h, h, plo, plo);
                    uint32_t off =
                        (uint32_t)((j * 512 + (int)rr * 64 + rc) * 16);
#pragma unroll
                    for (uint32_t rk = 0; rk < 8; rk++)
                        st_cluster_v4(mapa32(hb_s, rk) + off, v);
                    uint32_t fb = mb_s + (uint32_t)(j * 8 + (int)rr) * 8;
#pragma unroll
                    for (uint32_t rk = 0; rk < 8; rk++)
                        mbar_arrive_rel(mapa32(fb, rk));
                }
                xw_next = out[oidx + 512];
            }
        }
    }
    cluster_sync_();
}

// =====================================================================
extern "C" void kernel_launch(void* const* d_in, const int* in_sizes, int n_in,
                              void* d_out, int out_size) {
    const float* inputs = (const float*)d_in[0];  // (64,1024,256)
    const float* W_xh   = (const float*)d_in[1];  // (256,512)
    const float* W_hh   = (const float*)d_in[2];  // (512,512)
    const float* b_h    = (const float*)d_in[3];  // (512,)
    float* out = (float*)d_out;                   // (64,1024,512)

    cudaFuncSetAttribute(rnn_rec_kernel,
                         cudaFuncAttributeMaxDynamicSharedMemorySize,
                         K2_SMEM_BYTES);

    dim3 g1(4, 512);
    xw_gemm_kernel<<<g1, 256>>>(inputs, W_xh, b_h, out);

    rnn_rec_kernel<<<256, 256, K2_SMEM_BYTES>>>(W_hh, out);
}

// round 14
// speedup vs baseline: 1.5593x; 1.5593x over previous
#include <cuda_runtime.h>
#include <cuda_bf16.h>
#include <cstdint>

typedef unsigned long long u64;

// ---------------- packed fp32 + cluster helpers (sm_103a) ----------------
__device__ __forceinline__ u64 dup2(float x) {
    u64 r; asm("mov.b64 %0, {%1, %1};" : "=l"(r) : "f"(x)); return r;
}
__device__ __forceinline__ u64 fma2(u64 a, u64 b, u64 c) {
    u64 d; asm("fma.rn.f32x2 %0, %1, %2, %3;" : "=l"(d) : "l"(a), "l"(b), "l"(c));
    return d;
}
__device__ __forceinline__ u64 add2(u64 a, u64 b) {
    u64 d; asm("add.rn.f32x2 %0, %1, %2;" : "=l"(d) : "l"(a), "l"(b));
    return d;
}
__device__ __forceinline__ void unpack2(float& lo, float& hi, u64 v) {
    asm("mov.b64 {%0, %1}, %2;" : "=f"(lo), "=f"(hi) : "l"(v));
}
__device__ __forceinline__ u64 shfl_bfly_u64(u64 v, int m) {
    uint32_t lo, hi;
    asm("mov.b64 {%0, %1}, %2;" : "=r"(lo), "=r"(hi) : "l"(v));
    lo = __shfl_xor_sync(0xffffffffu, lo, m);
    hi = __shfl_xor_sync(0xffffffffu, hi, m);
    u64 r; asm("mov.b64 %0, {%1, %2};" : "=l"(r) : "r"(lo), "r"(hi));
    return r;
}
__device__ __forceinline__ uint32_t smem_u32(const void* p) {
    uint32_t a;
    asm("{ .reg .u64 t0; cvta.to.shared.u64 t0, %1; cvt.u32.u64 %0, t0; }"
        : "=r"(a) : "l"(p));
    return a;
}
__device__ __forceinline__ uint32_t mapa32(uint32_t saddr, uint32_t rank) {
    uint32_t r_;
    asm("mapa.shared::cluster.u32 %0, %1, %2;" : "=r"(r_) : "r"(saddr), "r"(rank));
    return r_;
}
__device__ __forceinline__ void st_cluster_v4(uint32_t addr, float4 v) {
    asm volatile("st.shared::cluster.v4.f32 [%0], {%1,%2,%3,%4};"
                 :: "r"(addr), "f"(v.x), "f"(v.y), "f"(v.z), "f"(v.w) : "memory");
}
__device__ __forceinline__ void mbar_init(uint32_t addr, uint32_t count) {
    asm volatile("mbarrier.init.shared.b64 [%0], %1;" :: "r"(addr), "r"(count) : "memory");
}
__device__ __forceinline__ void mbar_arrive_rel(uint32_t raddr) {
    asm volatile("mbarrier.arrive.release.cluster.shared::cluster.b64 _, [%0];"
                 :: "r"(raddr) : "memory");
}
__device__ __forceinline__ void mbar_wait_acq(uint32_t mbar, uint32_t parity) {
    asm volatile(
        "{\n\t"
        ".reg .pred P;\n\t"
        "MW_%=:\n\t"
        "mbarrier.try_wait.parity.acquire.cluster.shared::cta.b64 P, [%0], %1, 0x989680;\n\t"
        "@P bra.uni MD_%=;\n\t"
        "bra.uni MW_%=;\n\t"
        "MD_%=:\n\t"
        "}"
        :: "r"(mbar), "r"(parity) : "memory");
}
__device__ __forceinline__ uint32_t ctarank() {
    uint32_t r; asm("mov.u32 %0, %%cluster_ctarank;" : "=r"(r)); return r;
}
__device__ __forceinline__ void cluster_sync_() {
    asm volatile("barrier.cluster.arrive.aligned;" ::: "memory");
    asm volatile("barrier.cluster.wait.aligned;" ::: "memory");
}
// fast tanh: clamp then (e^2s - 1)/(e^2s + 1)
__device__ __forceinline__ float tanh_fast(float s) {
    float sc = fminf(fmaxf(s, -15.0f), 15.0f);
    float e  = __expf(2.0f * sc);
    return __fdividef(e - 1.0f, e + 1.0f);
}

// =====================================================================
// Kernel 1: out = inputs @ W_xh + b_h   (M=65536, K=256, N=512)
// 128x128x8 tile; LDG for the NEXT k-tile is issued before computing
// the current one (register staging), hiding gmem latency.
// =====================================================================
__global__ void __launch_bounds__(256)
xw_gemm_kernel(const float* __restrict__ A, const float* __restrict__ B,
               const float* __restrict__ bias, float* __restrict__ C) {
    __shared__ __align__(16) float As[8][128];
    __shared__ __align__(16) float Bs[8][128];
    const int tid = threadIdx.x;
    const int bn  = blockIdx.x;
    const int bm  = blockIdx.y;
    const int tx  = tid & 15;
    const int ty  = tid >> 4;
    const int arow = tid >> 1, acol = (tid & 1) << 2;
    const int brow = tid >> 5, bcol = (tid & 31) << 2;
    const float* Ab = A + (size_t)bm * 128 * 256;
    const float* Bb = B + bn * 128;

    u64 acc2[8][4];
#pragma unroll
    for (int i = 0; i < 8; i++)
#pragma unroll
        for (int j = 0; j < 4; j++) acc2[i][j] = 0ull;

    // preload tile 0 into registers
    float4 av = *(const float4*)(Ab + (size_t)arow * 256 + acol);
    float4 bv = *(const float4*)(Bb + (size_t)brow * 512 + bcol);

    for (int k0 = 0; k0 < 256; k0 += 8) {
        // stage current tile to smem
        As[acol + 0][arow] = av.x;
        As[acol + 1][arow] = av.y;
        As[acol + 2][arow] = av.z;
        As[acol + 3][arow] = av.w;
        *(float4*)&Bs[brow][bcol] = bv;
        __syncthreads();
        // issue next tile's LDG before compute (overlaps)
        if (k0 + 8 < 256) {
            av = *(const float4*)(Ab + (size_t)arow * 256 + (k0 + 8) + acol);
            bv = *(const float4*)(Bb + (size_t)(k0 + 8 + brow) * 512 + bcol);
        }
#pragma unroll
        for (int k = 0; k < 8; k++) {
            float4 a0 = *(const float4*)&As[k][ty * 8];
            float4 a1 = *(const float4*)&As[k][ty * 8 + 4];
            const u64* bp = (const u64*)&Bs[k][tx * 8];
            u64 b2[4];
#pragma unroll
            for (int j = 0; j < 4; j++) b2[j] = bp[j];
            u64 ad[8];
            ad[0] = dup2(a0.x); ad[1] = dup2(a0.y);
            ad[2] = dup2(a0.z); ad[3] = dup2(a0.w);
            ad[4] = dup2(a1.x); ad[5] = dup2(a1.y);
            ad[6] = dup2(a1.z); ad[7] = dup2(a1.w);
#pragma unroll
            for (int i = 0; i < 8; i++)
#pragma unroll
                for (int j = 0; j < 4; j++)
                    acc2[i][j] = fma2(ad[i], b2[j], acc2[i][j]);
        }
        __syncthreads();
    }

    float bi[8];
#pragma unroll
    for (int j = 0; j < 8; j++) bi[j] = bias[bn * 128 + tx * 8 + j];
#pragma unroll
    for (int i = 0; i < 8; i++) {
        size_t row = (size_t)bm * 128 + ty * 8 + i;
        float* cp = C + row * 512 + bn * 128 + tx * 8;
        float v[8];
#pragma unroll
        for (int j = 0; j < 4; j++) unpack2(v[2 * j], v[2 * j + 1], acc2[i][j]);
#pragma unroll
        for (int j = 0; j < 8; j++) v[j] += bi[j];
        *(float4*)(cp + 0) = make_float4(v[0], v[1], v[2], v[3]);
        *(float4*)(cp + 4) = make_float4(v[4], v[5], v[6], v[7]);
    }
}

// =====================================================================
// Kernel 2: recurrence. 32 clusters x 8 CTAs x 256 threads, 2 CTAs/SM.
// R11 structure (two syncs, stg staging, warp-w -> rank-w send, hoisted
// mapa, full[2][8] count-32 mbarriers) + NEW warp-internal half-combine:
// lanes half=0/1 hold the same columns for different k-halves; merge
// with shfl.bfly(16) + add.f32x2 -> only 8 partial slots, half the STS.
// =====================================================================
// float offsets in dynamic smem
#define WSM_OFF  0            // [8][64][16] u64 = 16384 floats (64 KB)
#define HB_OFF   16384        // [2][512][4] dup'd h = 4096 floats (16 KB)
#define RED_OFF  20480        // [16][33] u64 = 1056 floats
#define STG_OFF  (RED_OFF + 1056)          // [64][4] dup'd slice = 256 floats
#define MB_OFF   (STG_OFF + 256)           // full[2][8] = 16 mbarriers
#define K2_FLOATS (MB_OFF + 32)
#define K2_SMEM_BYTES (K2_FLOATS * 4)      // 87,296 B

__global__ void __launch_bounds__(256, 2) __cluster_dims__(8, 1, 1)
rnn_rec_kernel(const float* __restrict__ W_hh, float* __restrict__ out) {
    extern __shared__ __align__(16) float smem[];
    u64*   wsm = (u64*)(smem + WSM_OFF);
    float* hb  = smem + HB_OFF;
    float* red = smem + RED_OFF;
    float* stg = smem + STG_OFF;

    const int tid = threadIdx.x;
    const uint32_t rr = ctarank();
    const int w    = tid >> 5;          // warp 0..7
    const int ln   = tid & 31;
    const int half = ln >> 4;           // k-half within warp's 64-k range
    const int l15  = ln & 15;
    const int cluster = (int)(blockIdx.x >> 3);

    const int kbase = 64 * w + 32 * half;   // this lane's 32-k range start
    const int c0    = 4 * l15;              // first of 4 owned columns

    // ---- W: col-pair A (c0,c0+1) in regs; col-pair B (c0+2,c0+3) in smem ----
    u64 wregA[32];
    {
        const u64* wgA = (const u64*)(W_hh + (size_t)kbase * 512 +
                                      rr * 64 + c0);
#pragma unroll
        for (int kk = 0; kk < 32; kk++) wregA[kk] = wgA[(size_t)kk * 256];
        const u64* wgB = (const u64*)(W_hh + (size_t)kbase * 512 +
                                      rr * 64 + c0 + 2);
        for (int kk = 0; kk < 32; kk++)
            wsm[(size_t)(w * 64 + half * 32 + kk) * 16 + l15] =
                wgB[(size_t)kk * 256];
    }
    for (int i = tid; i < 4096; i += 256) hb[i] = 0.0f;

    // ---- mbarriers: full[2][8], count 32 ----
    const uint32_t mb_s = smem_u32(smem + MB_OFF);
    if (tid == 0) {
#pragma unroll
        for (int b = 0; b < 2; b++)
            for (int s = 0; s < 8; s++)
                mbar_init(mb_s + (b * 8 + s) * 8, 32);
    }
    __syncthreads();
    cluster_sync_();   // peers' inits + hb zeros visible before any remote op

    // reduce/output mapping (tid < 128): col rc, batch rb
    const int rc = tid & 63;
    const int rb = (tid >> 6) & 1;

    const uint32_t hb_s = smem_u32(hb);
    const uint32_t remHB = mapa32(hb_s, (uint32_t)w);
    const uint32_t remFA = mapa32(mb_s + (0 * 8 + (int)rr) * 8, (uint32_t)w);
    const uint32_t remFB = mapa32(mb_s + (1 * 8 + (int)rr) * 8, (uint32_t)w);
    const uint32_t fullW0 = mb_s + (0 * 8 + w) * 8;
    const uint32_t fullW1 = mb_s + (1 * 8 + w) * 8;

    u64* redu = (u64*)red;
    const int P0 = 2 * l15;            // col-pair indices P0, P0+1
    const size_t obase = ((size_t)(cluster * 2 + rb) * 1024) * 512 +
                         (size_t)rr * 64 + rc;
    const float4* stg4 = (const float4*)stg;
    const u64* wqB = wsm + (size_t)(w * 64 + half * 32) * 16 + l15;

    float xw_next = (tid < 128) ? out[obase] : 0.0f;

    int phF0 = 0, phF1 = 0;

    for (int t = 0; t < 1024; t++) {
        const int j  = t & 1;
        const int jr = j ^ 1;
        const float xw_v = xw_next;
        const size_t oidx = obase + (size_t)t * 512;

        // ---- wait only MY slice (from rank w) ----
        if (t > 0) {
            if (jr == 0) { mbar_wait_acq(fullW0, phF0); phF0 ^= 1; }
            else         { mbar_wait_acq(fullW1, phF1); phF1 ^= 1; }
        }

        // ---- GEMV: 2 col-pairs x 32 k per lane ----
        u64 aA0 = 0ull, aB0 = 0ull, aA1 = 0ull, aB1 = 0ull;
        const ulonglong2* hp =
            (const ulonglong2*)(hb + (size_t)(jr * 512 + kbase) * 4);
#pragma unroll
        for (int kk = 0; kk < 32; kk++) {
            ulonglong2 hv = hp[kk];          // {dup(h b0), dup(h b1)}
            u64 wA = wregA[kk];
            u64 wB = wqB[(size_t)kk * 16];
            aA0 = fma2(wA, hv.x, aA0);
            aB0 = fma2(wA, hv.y, aB0);
            aA1 = fma2(wB, hv.x, aA1);
            aB1 = fma2(wB, hv.y, aB1);
        }
        // combine the two k-halves (same columns) within the warp
        aA0 = add2(aA0, shfl_bfly_u64(aA0, 16));
        aB0 = add2(aB0, shfl_bfly_u64(aB0, 16));
        aA1 = add2(aA1, shfl_bfly_u64(aA1, 16));
        aB1 = add2(aB1, shfl_bfly_u64(aB1, 16));
        if (half == 0) {
            redu[(w * 2 + 0) * 33 + P0]     = aA0;
            redu[(w * 2 + 1) * 33 + P0]     = aB0;
            redu[(w * 2 + 0) * 33 + P0 + 1] = aA1;
            redu[(w * 2 + 1) * 33 + P0 + 1] = aB1;
        }
        __syncthreads();

        // ---- reduce 8 partials + xw, tanh, store, stage dup'd ----
        if (tid < 128) {
            float s = xw_v;
#pragma unroll
            for (int ww = 0; ww < 8; ww++)
                s += red[(ww * 2 + rb) * 66 + rc];
            float h = tanh_fast(s);
            out[oidx] = h;
            *(u64*)(stg + rc * 4 + rb * 2) = dup2(h);
        }
        __syncthreads();

        // ---- send my slice (dup'd, 1 KB) warp w -> rank w ----
        if (t < 1023) {
            float4 v0 = stg4[ln];
            float4 v1 = stg4[ln + 32];
            uint32_t base = (uint32_t)((j * 2048 + ((int)rr * 64) * 4) * 4);
            st_cluster_v4(remHB + base + (uint32_t)ln * 16, v0);
            st_cluster_v4(remHB + base + (uint32_t)(ln + 32) * 16, v1);
            mbar_arrive_rel(j == 0 ? remFA : remFB);
            if (tid < 128) xw_next = out[oidx + 512];
        }
    }
    cluster_sync_();
}

// =====================================================================
extern "C" void kernel_launch(void* const* d_in, const int* in_sizes, int n_in,
                              void* d_out, int out_size) {
    const float* inputs = (const float*)d_in[0];  // (64,1024,256)
    const float* W_xh   = (const float*)d_in[1];  // (256,512)
    const float* W_hh   = (const float*)d_in[2];  // (512,512)
    const float* b_h    = (const float*)d_in[3];  // (512,)
    float* out = (float*)d_out;                   // (64,1024,512)

    cudaFuncSetAttribute(rnn_rec_kernel,
                         cudaFuncAttributeMaxDynamicSharedMemorySize,
                         K2_SMEM_BYTES);

    dim3 g1(4, 512);
    xw_gemm_kernel<<<g1, 256>>>(inputs, W_xh, b_h, out);

    rnn_rec_kernel<<<256, 256, K2_SMEM_BYTES>>>(W_hh, out);
}

// round 15
// speedup vs baseline: 1.6813x; 1.0782x over previous
#include <cuda_runtime.h>
#include <cuda_bf16.h>
#include <cstdint>

typedef unsigned long long u64;

// ---------------- packed fp32 + cluster helpers (sm_103a) ----------------
__device__ __forceinline__ u64 dup2(float x) {
    u64 r; asm("mov.b64 %0, {%1, %1};" : "=l"(r) : "f"(x)); return r;
}
__device__ __forceinline__ u64 pack2(float lo, float hi) {
    u64 r; asm("mov.b64 %0, {%1, %2};" : "=l"(r) : "f"(lo), "f"(hi)); return r;
}
__device__ __forceinline__ u64 fma2(u64 a, u64 b, u64 c) {
    u64 d; asm("fma.rn.f32x2 %0, %1, %2, %3;" : "=l"(d) : "l"(a), "l"(b), "l"(c));
    return d;
}
__device__ __forceinline__ void unpack2(float& lo, float& hi, u64 v) {
    asm("mov.b64 {%0, %1}, %2;" : "=f"(lo), "=f"(hi) : "l"(v));
}
__device__ __forceinline__ float fold2(u64 v) {
    float lo, hi; unpack2(lo, hi, v); return lo + hi;
}
__device__ __forceinline__ uint32_t smem_u32(const void* p) {
    uint32_t a;
    asm("{ .reg .u64 t0; cvta.to.shared.u64 t0, %1; cvt.u32.u64 %0, t0; }"
        : "=r"(a) : "l"(p));
    return a;
}
__device__ __forceinline__ uint32_t mapa32(uint32_t saddr, uint32_t rank) {
    uint32_t r_;
    asm("mapa.shared::cluster.u32 %0, %1, %2;" : "=r"(r_) : "r"(saddr), "r"(rank));
    return r_;
}
__device__ __forceinline__ void st_cluster_v4(uint32_t addr, float4 v) {
    asm volatile("st.shared::cluster.v4.f32 [%0], {%1,%2,%3,%4};"
                 :: "r"(addr), "f"(v.x), "f"(v.y), "f"(v.z), "f"(v.w) : "memory");
}
__device__ __forceinline__ void mbar_init(uint32_t addr, uint32_t count) {
    asm volatile("mbarrier.init.shared.b64 [%0], %1;" :: "r"(addr), "r"(count) : "memory");
}
__device__ __forceinline__ void mbar_arrive_rel(uint32_t raddr) {
    asm volatile("mbarrier.arrive.release.cluster.shared::cluster.b64 _, [%0];"
                 :: "r"(raddr) : "memory");
}
__device__ __forceinline__ void mbar_wait_acq(uint32_t mbar, uint32_t parity) {
    asm volatile(
        "{\n\t"
        ".reg .pred P;\n\t"
        "MW_%=:\n\t"
        "mbarrier.try_wait.parity.acquire.cluster.shared::cta.b64 P, [%0], %1, 0x989680;\n\t"
        "@P bra.uni MD_%=;\n\t"
        "bra.uni MW_%=;\n\t"
        "MD_%=:\n\t"
        "}"
        :: "r"(mbar), "r"(parity) : "memory");
}
__device__ __forceinline__ uint32_t ctarank() {
    uint32_t r; asm("mov.u32 %0, %%cluster_ctarank;" : "=r"(r)); return r;
}
__device__ __forceinline__ void cluster_sync_() {
    asm volatile("barrier.cluster.arrive.aligned;" ::: "memory");
    asm volatile("barrier.cluster.wait.aligned;" ::: "memory");
}
// fast tanh: clamp then (e^2s - 1)/(e^2s + 1)
__device__ __forceinline__ float tanh_fast(float s) {
    float sc = fminf(fmaxf(s, -15.0f), 15.0f);
    float e  = __expf(2.0f * sc);
    return __fdividef(e - 1.0f, e + 1.0f);
}

// =====================================================================
// Kernel 1: out = inputs @ W_xh + b_h   (M=65536, K=256, N=512)
// 128x128x8 tile; next k-tile's LDG issued before current compute.
// =====================================================================
__global__ void __launch_bounds__(256)
xw_gemm_kernel(const float* __restrict__ A, const float* __restrict__ B,
               const float* __restrict__ bias, float* __restrict__ C) {
    __shared__ __align__(16) float As[8][128];
    __shared__ __align__(16) float Bs[8][128];
    const int tid = threadIdx.x;
    const int bn  = blockIdx.x;
    const int bm  = blockIdx.y;
    const int tx  = tid & 15;
    const int ty  = tid >> 4;
    const int arow = tid >> 1, acol = (tid & 1) << 2;
    const int brow = tid >> 5, bcol = (tid & 31) << 2;
    const float* Ab = A + (size_t)bm * 128 * 256;
    const float* Bb = B + bn * 128;

    u64 acc2[8][4];
#pragma unroll
    for (int i = 0; i < 8; i++)
#pragma unroll
        for (int j = 0; j < 4; j++) acc2[i][j] = 0ull;

    float4 av = *(const float4*)(Ab + (size_t)arow * 256 + acol);
    float4 bv = *(const float4*)(Bb + (size_t)brow * 512 + bcol);

    for (int k0 = 0; k0 < 256; k0 += 8) {
        As[acol + 0][arow] = av.x;
        As[acol + 1][arow] = av.y;
        As[acol + 2][arow] = av.z;
        As[acol + 3][arow] = av.w;
        *(float4*)&Bs[brow][bcol] = bv;
        __syncthreads();
        if (k0 + 8 < 256) {
            av = *(const float4*)(Ab + (size_t)arow * 256 + (k0 + 8) + acol);
            bv = *(const float4*)(Bb + (size_t)(k0 + 8 + brow) * 512 + bcol);
        }
#pragma unroll
        for (int k = 0; k < 8; k++) {
            float4 a0 = *(const float4*)&As[k][ty * 8];
            float4 a1 = *(const float4*)&As[k][ty * 8 + 4];
            const u64* bp = (const u64*)&Bs[k][tx * 8];
            u64 b2[4];
#pragma unroll
            for (int j = 0; j < 4; j++) b2[j] = bp[j];
            u64 ad[8];
            ad[0] = dup2(a0.x); ad[1] = dup2(a0.y);
            ad[2] = dup2(a0.z); ad[3] = dup2(a0.w);
            ad[4] = dup2(a1.x); ad[5] = dup2(a1.y);
            ad[6] = dup2(a1.z); ad[7] = dup2(a1.w);
#pragma unroll
            for (int i = 0; i < 8; i++)
#pragma unroll
                for (int j = 0; j < 4; j++)
                    acc2[i][j] = fma2(ad[i], b2[j], acc2[i][j]);
        }
        __syncthreads();
    }

    float bi[8];
#pragma unroll
    for (int j = 0; j < 8; j++) bi[j] = bias[bn * 128 + tx * 8 + j];
#pragma unroll
    for (int i = 0; i < 8; i++) {
        size_t row = (size_t)bm * 128 + ty * 8 + i;
        float* cp = C + row * 512 + bn * 128 + tx * 8;
        float v[8];
#pragma unroll
        for (int j = 0; j < 4; j++) unpack2(v[2 * j], v[2 * j + 1], acc2[i][j]);
#pragma unroll
        for (int j = 0; j < 8; j++) v[j] += bi[j];
        *(float4*)(cp + 0) = make_float4(v[0], v[1], v[2], v[3]);
        *(float4*)(cp + 4) = make_float4(v[4], v[5], v[6], v[7]);
    }
}

// =====================================================================
// Kernel 2: recurrence. 32 clusters x 8 CTAs x 256 threads, 2 CTAs/SM.
// R13 protocol (full[2][8] cnt-32 mbarriers, warp-w -> rank-w send,
// hoisted mapa, two syncs). NEW: k-pair f32x2 packing — h is sent and
// stored NON-duplicated (DSMEM bytes halved: 4 KB out + 4 KB in /CTA).
//   hb[buf][256 kpairs][4] = {h_b0[2i], h_b0[2i+1], h_b1[2i], h_b1[2i+1]}
//   lane ln of warp w owns cols (2ln, 2ln+1); acc u64 = {even-k, odd-k}
//   partials, folded after the loop. W pre-packed into k-pair u64s
//   (col 2ln in regs, col 2ln+1 in smem).
// =====================================================================
// float offsets in dynamic smem
#define WSM_OFF  0            // [8][32][32] u64 = 16384 floats (64 KB)
#define HB_OFF   16384        // [2][256][4] h = 2048 floats (8 KB)
#define RED_OFF  18432        // [16][66] floats = 1056
#define STG_OFF  (RED_OFF + 1056)          // [32][4] slice = 128 floats
#define MB_OFF   (STG_OFF + 128)           // full[2][8] = 16 mbarriers
#define K2_FLOATS (MB_OFF + 32)
#define K2_SMEM_BYTES (K2_FLOATS * 4)      // 78,592 B

__global__ void __launch_bounds__(256, 2) __cluster_dims__(8, 1, 1)
rnn_rec_kernel(const float* __restrict__ W_hh, float* __restrict__ out) {
    extern __shared__ __align__(16) float smem[];
    u64*   wsm = (u64*)(smem + WSM_OFF);
    float* hb  = smem + HB_OFF;
    float* red = smem + RED_OFF;
    float* stg = smem + STG_OFF;

    const int tid = threadIdx.x;
    const uint32_t rr = ctarank();
    const int w  = tid >> 5;            // warp 0..7; k in [64w, 64w+64)
    const int ln = tid & 31;
    const int c0 = 2 * ln;              // cols c0, c0+1
    const int cluster = (int)(blockIdx.x >> 3);

    // ---- W: k-pair packed. col c0 -> regs, col c0+1 -> smem ----
    u64 wregA[32];
    {
        const float* wg = W_hh + (size_t)(64 * w) * 512 + rr * 64 + c0;
#pragma unroll
        for (int kk = 0; kk < 32; kk++) {
            // rows 2kk and 2kk+1; cols c0, c0+1 adjacent -> 2 LDG.64
            float2 r0 = *(const float2*)(wg + (size_t)(2 * kk) * 512);
            float2 r1 = *(const float2*)(wg + (size_t)(2 * kk + 1) * 512);
            wregA[kk] = pack2(r0.x, r1.x);                  // col c0
            wsm[(size_t)(w * 32 + kk) * 32 + ln] = pack2(r0.y, r1.y); // col c0+1
        }
    }
    for (int i = tid; i < 2048; i += 256) hb[i] = 0.0f;

    // ---- mbarriers: full[2][8], count 32 ----
    const uint32_t mb_s = smem_u32(smem + MB_OFF);
    if (tid == 0) {
#pragma unroll
        for (int b = 0; b < 2; b++)
            for (int s = 0; s < 8; s++)
                mbar_init(mb_s + (b * 8 + s) * 8, 32);
    }
    __syncthreads();
    cluster_sync_();   // peers' inits + hb zeros visible before any remote op

    // reduce/output mapping (tid < 128): col rc, batch rb
    const int rc = tid & 63;
    const int rb = (tid >> 6) & 1;

    const uint32_t hb_s = smem_u32(hb);
    const uint32_t remHB = mapa32(hb_s, (uint32_t)w);
    const uint32_t remFA = mapa32(mb_s + (0 * 8 + (int)rr) * 8, (uint32_t)w);
    const uint32_t remFB = mapa32(mb_s + (1 * 8 + (int)rr) * 8, (uint32_t)w);
    const uint32_t fullW0 = mb_s + (0 * 8 + w) * 8;
    const uint32_t fullW1 = mb_s + (1 * 8 + w) * 8;

    const size_t obase = ((size_t)(cluster * 2 + rb) * 1024) * 512 +
                         (size_t)rr * 64 + rc;
    const float4* stg4 = (const float4*)stg;
    const u64* wqB = wsm + (size_t)(w * 32) * 32 + ln;
    // stg index for reducer: kpair = rc>>1, pos = rb*2 + (rc&1)
    const int stg_idx = (rc >> 1) * 4 + rb * 2 + (rc & 1);

    float xw_next = (tid < 128) ? out[obase] : 0.0f;

    int phF0 = 0, phF1 = 0;

    for (int t = 0; t < 1024; t++) {
        const int j  = t & 1;
        const int jr = j ^ 1;
        const float xw_v = xw_next;
        const size_t oidx = obase + (size_t)t * 512;

        // ---- wait only MY slice (from rank w) ----
        if (t > 0) {
            if (jr == 0) { mbar_wait_acq(fullW0, phF0); phF0 ^= 1; }
            else         { mbar_wait_acq(fullW1, phF1); phF1 ^= 1; }
        }

        // ---- GEMV: k-pair packed, 2 cols x 2 batches per lane ----
        u64 a00 = 0ull, a01 = 0ull, a10 = 0ull, a11 = 0ull;
        const ulonglong2* hp =
            (const ulonglong2*)(hb + (size_t)jr * 1024) + w * 32;
#pragma unroll
        for (int kk = 0; kk < 32; kk++) {
            ulonglong2 hv = hp[kk];   // hv.x={b0e,b0o}, hv.y={b1e,b1o}
            u64 wA = wregA[kk];
            u64 wB = wqB[(size_t)kk * 32];
            a00 = fma2(wA, hv.x, a00);   // col c0,   b0
            a01 = fma2(wA, hv.y, a01);   // col c0,   b1
            a10 = fma2(wB, hv.x, a10);   // col c0+1, b0
            a11 = fma2(wB, hv.y, a11);   // col c0+1, b1
        }
        // fold even/odd partials and store to red (packed col-pair STS.64)
        {
            float s00 = fold2(a00), s10 = fold2(a10);   // b0: cols c0, c0+1
            float s01 = fold2(a01), s11 = fold2(a11);   // b1
            *(u64*)(red + (w * 2 + 0) * 66 + c0) = pack2(s00, s10);
            *(u64*)(red + (w * 2 + 1) * 66 + c0) = pack2(s01, s11);
        }
        __syncthreads();

        // ---- reduce 8 partials + xw, tanh, store, stage (non-dup'd) ----
        if (tid < 128) {
            float s = xw_v;
#pragma unroll
            for (int ww = 0; ww < 8; ww++)
                s += red[(ww * 2 + rb) * 66 + rc];
            float h = tanh_fast(s);
            out[oidx] = h;
            stg[stg_idx] = h;
        }
        __syncthreads();

        // ---- send my slice (512 B) warp w -> rank w ----
        if (t < 1023) {
            float4 v = stg4[ln];      // one k-pair group {b0e,b0o,b1e,b1o}
            uint32_t dst = remHB +
                (uint32_t)(j * 4096 + ((int)rr * 32 + ln) * 16);
            st_cluster_v4(dst, v);
            mbar_arrive_rel(j == 0 ? remFA : remFB);
            if (tid < 128) xw_next = out[oidx + 512];
        }
    }
    cluster_sync_();
}

// =====================================================================
extern "C" void kernel_launch(void* const* d_in, const int* in_sizes, int n_in,
                              void* d_out, int out_size) {
    const float* inputs = (const float*)d_in[0];  // (64,1024,256)
    const float* W_xh   = (const float*)d_in[1];  // (256,512)
    const float* W_hh   = (const float*)d_in[2];  // (512,512)
    const float* b_h    = (const float*)d_in[3];  // (512,)
    float* out = (float*)d_out;                   // (64,1024,512)

    cudaFuncSetAttribute(rnn_rec_kernel,
                         cudaFuncAttributeMaxDynamicSharedMemorySize,
                         K2_SMEM_BYTES);

    dim3 g1(4, 512);
    xw_gemm_kernel<<<g1, 256>>>(inputs, W_xh, b_h, out);

    rnn_rec_kernel<<<256, 256, K2_SMEM_BYTES>>>(W_hh, out);
}